// round 9
// baseline (speedup 1.0000x reference)
#include <cuda_runtime.h>

#define NV   1024
#define NH4  4096          // float4 per harm row
#define ROW4 8192          // float4 per output row

// -------- device scratch (no allocations allowed) --------
__device__ float4 g_energy[NV];            // e_low, e_mid, e_high, total_before
__device__ volatile unsigned g_gen;        // barrier generation (zero-init, monotone)
__device__ unsigned g_count;               // barrier arrival counter (self-resetting)

__device__ __forceinline__ void stcs4(float4* p, float4 v) {
    asm volatile("st.global.cs.v4.f32 [%0], {%1,%2,%3,%4};"
                 :: "l"(p), "f"(v.x), "f"(v.y), "f"(v.z), "f"(v.w) : "memory");
}
__device__ __forceinline__ float4 ldcs4(const float4* p) {
    float4 v;
    asm volatile("ld.global.cs.v4.f32 {%0,%1,%2,%3}, [%4];"
                 : "=f"(v.x), "=f"(v.y), "=f"(v.z), "=f"(v.w) : "l"(p));
    return v;
}
__device__ __forceinline__ float4 ldcg4(const float4* p) {
    float4 v;
    asm volatile("ld.global.cg.v4.f32 {%0,%1,%2,%3}, [%4];"
                 : "=f"(v.x), "=f"(v.y), "=f"(v.z), "=f"(v.w) : "l"(p));
    return v;
}

// One fused persistent kernel: 1024 blocks (one per voice) x 256 threads, all co-resident.
//   phase 1: block v reduces harm row v -> g_energy[v]
//   grid barrier (generation counter; safe across graph replays)
//   phase 2: every block computes global totals + its own voice's gains
//   phase 3: block v applies gains to row v (harm from L1/L2; noise streamed)
__global__ void __launch_bounds__(256, 7) fused_kernel(
    const float* __restrict__ harm, const float* __restrict__ noise,
    const float* __restrict__ f0_hz, const float* __restrict__ cw,
    const float* __restrict__ wdr, const unsigned int* __restrict__ isa,
    float* __restrict__ out)
{
    const int v   = blockIdx.x;
    const int tid = threadIdx.x;
    const unsigned m = 0xFFFFFFFFu;
    const int lane = tid & 31, wid = tid >> 5;

    __shared__ float3 swp[8];
    __shared__ float  sred[8][5];
    __shared__ float  tot[5];
    __shared__ float4 s_mult;
    __shared__ int2   s_kb;
    __shared__ unsigned s_bytemode;

    const float f0 = f0_hz[v];
    const float4* row = reinterpret_cast<const float4*>(harm) + (size_t)v * NH4;

    // ---- is_active encoding detection (words 0..255 are in-bounds in all modes) ----
    if (tid == 0) s_bytemode = 0u;
    __syncthreads();
    {
        unsigned w = isa[tid];
        bool weird = (w > 1u) && (w != 0x3F800000u);
        unsigned any = __ballot_sync(m, weird);
        if (any && (lane == 0)) atomicOr(&s_bytemode, 1u);
    }

    // ---- phase 1: row reduction (bands live entirely in h <= 64) ----
    float e0 = 0.f, e1 = 0.f;
    float a0 = 0.f, a1 = 0.f, a2 = 0.f, a3 = 0.f;
    {
        float4 x = row[tid];
        if (tid < 16) {
            const int h = 4 * tid + 1;
            float f;
            f = f0 * (float)(h);     if (f < 500.f) e0 += x.x; else if (f < 2000.f) e1 += x.x; else a0 += x.x;
            f = f0 * (float)(h + 1); if (f < 500.f) e0 += x.y; else if (f < 2000.f) e1 += x.y; else a1 += x.y;
            f = f0 * (float)(h + 2); if (f < 500.f) e0 += x.z; else if (f < 2000.f) e1 += x.z; else a2 += x.z;
            f = f0 * (float)(h + 3); if (f < 500.f) e0 += x.w; else if (f < 2000.f) e1 += x.w; else a3 += x.w;
        } else {
            a0 += x.x; a1 += x.y; a2 += x.z; a3 += x.w;
        }
    }
    #pragma unroll
    for (int it = 1; it < 16; ++it) {
        float4 x = row[tid + it * 256];
        a0 += x.x; a1 += x.y; a2 += x.z; a3 += x.w;
    }
    float e2 = (a0 + a1) + (a2 + a3);

    #pragma unroll
    for (int o = 16; o; o >>= 1) {
        e0 += __shfl_down_sync(m, e0, o);
        e1 += __shfl_down_sync(m, e1, o);
        e2 += __shfl_down_sync(m, e2, o);
    }
    if (lane == 0) swp[wid] = make_float3(e0, e1, e2);
    __syncthreads();
    if (wid == 0) {
        float3 a = (lane < 8) ? swp[lane] : make_float3(0.f, 0.f, 0.f);
        #pragma unroll
        for (int o = 4; o; o >>= 1) {
            a.x += __shfl_down_sync(m, a.x, o);
            a.y += __shfl_down_sync(m, a.y, o);
            a.z += __shfl_down_sync(m, a.z, o);
        }
        if (lane == 0) g_energy[v] = make_float4(a.x, a.y, a.z, a.x + a.y + a.z);
    }
    __syncthreads();

    // ---- grid barrier (all 1024 blocks guaranteed co-resident) ----
    if (tid == 0) {
        __threadfence();                       // publish g_energy[v]
        unsigned gen = g_gen;
        if (atomicAdd(&g_count, 1u) == (unsigned)(gridDim.x - 1)) {
            g_count = 0u;
            __threadfence();
            g_gen = gen + 1u;                  // release
        } else {
            while (g_gen == gen) __nanosleep(64);
        }
    }
    __syncthreads();

    // ---- phase 2: global totals (each block redundantly; 16KB of L2 reads) ----
    const bool bmode = (s_bytemode != 0u);
    float r0 = 0.f, r1 = 0.f, r2 = 0.f, r3 = 0.f, r4 = 0.f;
    #pragma unroll
    for (int k = 0; k < 4; ++k) {
        const int u = tid + k * 256;
        const float act = bmode ? (reinterpret_cast<const unsigned char*>(isa)[u] ? 1.f : 0.f)
                                : (isa[u] ? 1.f : 0.f);
        float4 e = ldcg4(&g_energy[u]);
        r0 += e.x * act; r1 += e.y * act; r2 += e.z * act;
        r3 += cw[u] * act; r4 += act;
    }
    #pragma unroll
    for (int o = 16; o; o >>= 1) {
        r0 += __shfl_down_sync(m, r0, o);
        r1 += __shfl_down_sync(m, r1, o);
        r2 += __shfl_down_sync(m, r2, o);
        r3 += __shfl_down_sync(m, r3, o);
        r4 += __shfl_down_sync(m, r4, o);
    }
    if (lane == 0) {
        sred[wid][0] = r0; sred[wid][1] = r1; sred[wid][2] = r2;
        sred[wid][3] = r3; sred[wid][4] = r4;
    }
    __syncthreads();
    if (wid == 0 && lane < 8) {
        float b0 = sred[lane][0], b1 = sred[lane][1], b2 = sred[lane][2];
        float b3 = sred[lane][3], b4 = sred[lane][4];
        #pragma unroll
        for (int o = 4; o; o >>= 1) {
            b0 += __shfl_down_sync(0xFFu, b0, o);
            b1 += __shfl_down_sync(0xFFu, b1, o);
            b2 += __shfl_down_sync(0xFFu, b2, o);
            b3 += __shfl_down_sync(0xFFu, b3, o);
            b4 += __shfl_down_sync(0xFFu, b4, o);
        }
        if (lane == 0) { tot[0]=b0; tot[1]=b1; tot[2]=b2; tot[3]=b3; tot[4]=b4; }
    }
    __syncthreads();

    // ---- own-voice gains + integer band bounds (thread 0) ----
    if (tid == 0) {
        int k1 = 0, k2 = 0;
        #pragma unroll
        for (int h = 1; h <= 64; ++h) {
            float f = f0 * (float)h;
            if (f < 500.f)  ++k1;
            if (f < 2000.f) ++k2;
        }
        s_kb = make_int2(k1, k2);

        const bool active = bmode ? (reinterpret_cast<const unsigned char*>(isa)[v] != 0)
                                  : (isa[v] != 0u);
        const float actf = active ? 1.0f : 0.0f;
        const float w = cw[v];
        const float4 e = ldcg4(&g_energy[v]);

        const float TE[3] = { tot[0], tot[1], tot[2] };
        const float TW = fmaxf(tot[3], 1e-6f);
        const bool changed = (tot[4] >= 1.5f);          // n_active >= 2

        const float my_share = (w / TW) * 0.5f;
        const float en[3] = { e.x * actf, e.y * actf, e.z * actf };

        float g[3];
        #pragma unroll
        for (int b = 0; b < 3; ++b) {
            const float ex  = en[b] - my_share;
            const float er  = ex / fmaxf(en[b], 1e-6f);
            const float red = fmaxf(0.3f, 1.0f - wdr[3 * v + b] * er * 0.5f);
            const bool apply = (TE[b] > 0.5f) && (en[b] > 0.0f) && (ex > 0.0f) && active;
            g[b] = apply ? red : 1.0f;
        }
        const float total_after  = g[0] * e.x + g[1] * e.y + g[2] * e.z;
        const float ns = (e.w > 1e-6f) ? (total_after / e.w) : 1.0f;

        float4 mult;
        mult.x = changed ? g[0] : 1.0f;
        mult.y = changed ? g[1] : 1.0f;
        mult.z = changed ? g[2] : 1.0f;
        mult.w = (changed && active) ? ns : 1.0f;
        s_mult = mult;
    }
    __syncthreads();

    // ---- phase 3: apply. harm row v is L1/L2-hot from phase 1. ----
    const float4 g = s_mult;
    const int2 kb = s_kb;
    float4* dst = reinterpret_cast<float4*>(out) + (size_t)v * ROW4;

    // harm: iteration 0 carries the band boundaries
    {
        float4 x = row[tid];
        const int h = 4 * tid + 1;
        float4 o;
        o.x = x.x * ((h    ) <= kb.x ? g.x : ((h    ) <= kb.y ? g.y : g.z));
        o.y = x.y * ((h + 1) <= kb.x ? g.x : ((h + 1) <= kb.y ? g.y : g.z));
        o.z = x.z * ((h + 2) <= kb.x ? g.x : ((h + 2) <= kb.y ? g.y : g.z));
        o.w = x.w * ((h + 3) <= kb.x ? g.x : ((h + 3) <= kb.y ? g.y : g.z));
        stcs4(dst + tid, o);
    }
    {
        const float s = g.z;
        #pragma unroll
        for (int it = 1; it < 16; ++it) {
            float4 x = row[tid + it * 256];
            stcs4(dst + tid + it * 256,
                  make_float4(x.x * s, x.y * s, x.z * s, x.w * s));
        }
    }
    // noise: streaming
    {
        const float4* nrow = reinterpret_cast<const float4*>(noise) + (size_t)v * NH4;
        const float s = g.w;
        #pragma unroll
        for (int it = 0; it < 16; ++it) {
            float4 x = ldcs4(nrow + tid + it * 256);
            stcs4(dst + NH4 + tid + it * 256,
                  make_float4(x.x * s, x.y * s, x.z * s, x.w * s));
        }
    }
}

extern "C" void kernel_launch(void* const* d_in, const int* in_sizes, int n_in,
                              void* d_out, int out_size) {
    const float*        harm  = (const float*)d_in[0];
    const float*        noise = (const float*)d_in[1];
    const float*        f0    = (const float*)d_in[2];
    const float*        cw    = (const float*)d_in[3];
    const float*        wdr   = (const float*)d_in[4];
    const unsigned int* isa   = (const unsigned int*)d_in[5];
    float*              out   = (float*)d_out;

    fused_kernel<<<NV, 256>>>(harm, noise, f0, cw, wdr, isa, out);
}